// round 15
// baseline (speedup 1.0000x reference)
#include <cuda_runtime.h>
#include <cuda_fp16.h>
#include <stdint.h>

// ---------------------------------------------------------------------------
// ProteinEncoder 3-layer GCN. fp16 mma.sync GEMM 128x128/BK64/3-stage.
// Layer-1 GEMM reads fp32 x directly (fused convert in A-load) -> k_cvt gone.
// h fp16. half2 CSR agg x8. R13 stream topology (prep on side stream).
// ---------------------------------------------------------------------------

#define MAX_N 50000
#define MPAD  50048            // 391 * 128
#define MAX_E 600000

__device__ __half g_h16[(size_t)MAX_N * 512];        // GEMM output (fp16)
__device__ __half g_a16[(size_t)MAX_N * 512];        // agg output (fp16, layers 2/3 input)
__device__ __half g_w1[512 * 1280];                  // W1^T [512,1280]
__device__ __half g_w2[384 * 512];                   // W2^T [384,512]
__device__ __half g_w3[384 * 320];                   // W3^T [384,320]

__device__ int   g_deg[MAX_N];
__device__ float g_dinv[MAX_N];
__device__ int   g_start[MAX_N];
__device__ int   g_scan[MAX_N];
__device__ int   g_cursor[MAX_N];
__device__ int   g_csr_src[MAX_E];
__device__ int   g_bsum[256];

// ---------------------------------------------------------------------------
// helpers
// ---------------------------------------------------------------------------
__device__ __forceinline__ uint32_t smem_u32(const void* p) {
    uint32_t r;
    asm("{ .reg .u64 t; cvta.to.shared.u64 t, %1; cvt.u32.u64 %0, t; }"
        : "=r"(r) : "l"(p));
    return r;
}
__device__ __forceinline__ void ldsm4(uint32_t& r0, uint32_t& r1, uint32_t& r2,
                                      uint32_t& r3, uint32_t addr) {
    asm volatile("ldmatrix.sync.aligned.m8n8.x4.shared.b16 {%0,%1,%2,%3}, [%4];"
                 : "=r"(r0), "=r"(r1), "=r"(r2), "=r"(r3) : "r"(addr));
}
__device__ __forceinline__ void mma16816(float* c, const uint32_t* a,
                                         uint32_t b0, uint32_t b1) {
    asm volatile(
        "mma.sync.aligned.m16n8k16.row.col.f32.f16.f16.f32 "
        "{%0,%1,%2,%3}, {%4,%5,%6,%7}, {%8,%9}, {%0,%1,%2,%3};"
        : "+f"(c[0]), "+f"(c[1]), "+f"(c[2]), "+f"(c[3])
        : "r"(a[0]), "r"(a[1]), "r"(a[2]), "r"(a[3]), "r"(b0), "r"(b1));
}
__device__ __forceinline__ void cp16(uint32_t smem, const void* gmem) {
    asm volatile("cp.async.cg.shared.global [%0], [%1], 16;"
                 :: "r"(smem), "l"(gmem));
}
__device__ __forceinline__ void cp_commit() {
    asm volatile("cp.async.commit_group;" ::: "memory");
}
template <int NN>
__device__ __forceinline__ void cp_wait() {
    asm volatile("cp.async.wait_group %0;" :: "n"(NN) : "memory");
}
__device__ __forceinline__ void sts64(uint32_t addr, uint32_t v0, uint32_t v1) {
    asm volatile("st.shared.v2.b32 [%0], {%1,%2};" :: "r"(addr), "r"(v0), "r"(v1)
                 : "memory");
}

// ---------------------------------------------------------------------------
// CSR build
// ---------------------------------------------------------------------------
__global__ void k_zero(int n) {
    int i = blockIdx.x * blockDim.x + threadIdx.x;
    if (i < n) { g_deg[i] = 0; g_cursor[i] = 0; }
}
__global__ void k_hist(const int* __restrict__ dst, int E, int n) {
    int e = blockIdx.x * blockDim.x + threadIdx.x;
    if (e < E) {
        int d = dst[e];
        if (d >= 0 && d < n) atomicAdd(&g_deg[d], 1);
    }
}
__global__ void k_scan_block(int n) {
    __shared__ int sh[256];
    int t = threadIdx.x;
    int i = blockIdx.x * 256 + t;
    int v = (i < n) ? g_deg[i] : 0;
    sh[t] = v;
    __syncthreads();
    #pragma unroll
    for (int off = 1; off < 256; off <<= 1) {
        int x = (t >= off) ? sh[t - off] : 0;
        __syncthreads();
        sh[t] += x;
        __syncthreads();
    }
    if (i < n) g_scan[i] = sh[t];
    if (t == 255) g_bsum[blockIdx.x] = sh[255];
}
__global__ void k_scan_top(int nb) {
    __shared__ int sh[256];
    int t = threadIdx.x;
    int v = (t < nb) ? g_bsum[t] : 0;
    sh[t] = v;
    __syncthreads();
    #pragma unroll
    for (int off = 1; off < 256; off <<= 1) {
        int x = (t >= off) ? sh[t - off] : 0;
        __syncthreads();
        sh[t] += x;
        __syncthreads();
    }
    if (t < nb) g_bsum[t] = sh[t] - v;
}
__global__ void k_finish(int n) {
    int i = blockIdx.x * blockDim.x + threadIdx.x;
    if (i < n) {
        g_start[i] = g_scan[i] - g_deg[i] + g_bsum[i >> 8];
        g_dinv[i]  = rsqrtf((float)(g_deg[i] + 1));
    }
}
__global__ void k_fill(const int* __restrict__ src,
                       const int* __restrict__ dst, int E, int n) {
    int e = blockIdx.x * blockDim.x + threadIdx.x;
    if (e < E) {
        int d = dst[e];
        int s = src[e];
        if (d >= 0 && d < n && s >= 0 && s < n) {
            int p = atomicAdd(&g_cursor[d], 1);
            g_csr_src[g_start[d] + p] = s;
        }
    }
}

// W [K,N] fp32 -> W^T [Npad,Kpad] fp16, zero-padded
__global__ void k_wt(const float* __restrict__ W, __half* __restrict__ wt,
                     int K, int N, int Kpad, int Npad) {
    int idx = blockIdx.x * blockDim.x + threadIdx.x;
    if (idx < Npad * Kpad) {
        int n = idx / Kpad, k = idx - n * Kpad;
        float v = (n < N && k < K) ? W[(size_t)k * N + n] : 0.f;
        wt[idx] = __float2half_rn(v);
    }
}

// ---------------------------------------------------------------------------
// GEMM common geometry: 128x128 CTA, BK=64, 3 stages, 256 threads (8 warps
// 4x2, warp tile 32x64). Proven config (R9: 272us layer1, tensor 40%).
// ---------------------------------------------------------------------------
#define LDS 72
#define STAGE_ELEMS (128 * LDS)
#define STAGE_BYTES (STAGE_ELEMS * 2)
#define NSTAGE 3

// inner mainloop body shared by both variants (macro to keep identical SASS)
#define GEMM_COMPUTE_STAGE(aB, bB)                                             \
    _Pragma("unroll")                                                          \
    for (int ks = 0; ks < 4; ks++) {                                           \
        const uint32_t kofs = (uint32_t)(ks * 16) * 2;                         \
        uint32_t a[2][4];                                                      \
        _Pragma("unroll")                                                      \
        for (int mi = 0; mi < 2; mi++)                                         \
            ldsm4(a[mi][0], a[mi][1], a[mi][2], a[mi][3],                      \
                  (aB) + (aoffElem + (uint32_t)(mi * 16) * LDS) * 2 + kofs);   \
        uint32_t b[4][4];                                                      \
        _Pragma("unroll")                                                      \
        for (int nb = 0; nb < 4; nb++)                                         \
            ldsm4(b[nb][0], b[nb][1], b[nb][2], b[nb][3],                      \
                  (bB) + (boffElem + (uint32_t)(nb * 16) * LDS) * 2 + kofs);   \
        _Pragma("unroll")                                                      \
        for (int mi = 0; mi < 2; mi++)                                         \
            _Pragma("unroll")                                                  \
            for (int nb = 0; nb < 4; nb++) {                                   \
                mma16816(acc[mi][nb * 2 + 0], a[mi], b[nb][0], b[nb][1]);      \
                mma16816(acc[mi][nb * 2 + 1], a[mi], b[nb][2], b[nb][3]);      \
            }                                                                  \
    }

#define GEMM_EPILOGUE()                                                        \
    const int g = lane >> 2, tg = lane & 3;                                    \
    _Pragma("unroll")                                                          \
    for (int mi = 0; mi < 2; mi++) {                                           \
        _Pragma("unroll")                                                      \
        for (int nj = 0; nj < 8; nj++) {                                       \
            int col = n0 + wn * 64 + nj * 8 + tg * 2;                          \
            int mrow = m0 + wm * 32 + mi * 16 + g;                             \
            _Pragma("unroll")                                                  \
            for (int hf = 0; hf < 2; hf++) {                                   \
                int r = mrow + hf * 8;                                         \
                if (r < M && col + 2 <= Nout) {                                \
                    __half2 v = __floats2half2_rn(acc[mi][nj][hf * 2 + 0],     \
                                                  acc[mi][nj][hf * 2 + 1]);    \
                    *(__half2*)(C + (size_t)r * Nout + col) = v;               \
                }                                                              \
            }                                                                  \
        }                                                                      \
    }

// ---- variant A: fp16 A via cp.async (layers 2/3) ----
__global__ __launch_bounds__(256) void fp16_gemm(
    const __half* __restrict__ A, int lda,
    const __half* __restrict__ B, int ldb,
    __half* __restrict__ C, int M, int Nout, int K) {
    extern __shared__ __half sm[];
    __half* As = sm;
    __half* Bs = sm + NSTAGE * STAGE_ELEMS;

    const int tid = threadIdx.x;
    const int lane = tid & 31;
    const int wid = tid >> 5;
    const int wm = wid >> 1;
    const int wn = wid & 1;
    const int m0 = blockIdx.y * 128;
    const int n0 = blockIdx.x * 128;

    const int crow = tid >> 1;
    const int cseg = (tid & 1) * 4;

    float acc[2][8][4];
    #pragma unroll
    for (int i = 0; i < 2; i++)
        #pragma unroll
        for (int j = 0; j < 8; j++)
            #pragma unroll
            for (int q = 0; q < 4; q++) acc[i][j][q] = 0.f;

    const int NT = K / 64;

    const uint32_t aBase = smem_u32(As);
    const uint32_t bBase = smem_u32(Bs);
    const uint32_t aoffElem = (uint32_t)((wm * 32 + (lane & 15)) * LDS + (lane >> 4) * 8);
    const uint32_t boffElem = (uint32_t)((wn * 64 + ((lane >> 4) << 3) + (lane & 7)) * LDS +
                                         ((lane >> 3) & 1) * 8);
    const uint32_t cpOff = (uint32_t)(crow * LDS + cseg * 8) * 2;

    auto issue = [&](int nit) {
        const int k0 = nit * 64;
        const int st = nit % NSTAGE;
        const uint32_t sa = aBase + st * STAGE_BYTES + cpOff;
        const uint32_t sb = bBase + st * STAGE_BYTES + cpOff;
        const __half* ga = A + (size_t)(m0 + crow) * lda + k0 + cseg * 8;
        const __half* gb = B + (size_t)(n0 + crow) * ldb + k0 + cseg * 8;
        #pragma unroll
        for (int i = 0; i < 4; i++) cp16(sa + i * 16, ga + i * 8);
        #pragma unroll
        for (int i = 0; i < 4; i++) cp16(sb + i * 16, gb + i * 8);
        cp_commit();
    };

    issue(0);
    if (NT > 1) issue(1);

    for (int it = 0; it < NT; it++) {
        cp_wait<NSTAGE - 2>();
        __syncthreads();
        const int st = it % NSTAGE;
        const uint32_t aB = aBase + st * STAGE_BYTES;
        const uint32_t bB = bBase + st * STAGE_BYTES;
        GEMM_COMPUTE_STAGE(aB, bB)
        if (it + NSTAGE - 1 < NT) issue(it + NSTAGE - 1);
    }

    GEMM_EPILOGUE()
}

// ---- variant B: fp32 A with fused convert (layer 1; A = raw x) ----
__global__ __launch_bounds__(256) void fp16_gemm_f32a(
    const float* __restrict__ A, int lda,
    const __half* __restrict__ B, int ldb,
    __half* __restrict__ C, int M, int Nout, int K) {
    extern __shared__ __half sm[];
    __half* As = sm;
    __half* Bs = sm + NSTAGE * STAGE_ELEMS;

    const int tid = threadIdx.x;
    const int lane = tid & 31;
    const int wid = tid >> 5;
    const int wm = wid >> 1;
    const int wn = wid & 1;
    const int m0 = blockIdx.y * 128;
    const int n0 = blockIdx.x * 128;

    const int crow = tid >> 1;
    const int cseg = (tid & 1) * 4;

    // clamp pad rows (m0+crow may exceed M-1 on the last tile; x has no pad)
    int arow = m0 + crow;
    if (arow > M - 1) arow = M - 1;

    float acc[2][8][4];
    #pragma unroll
    for (int i = 0; i < 2; i++)
        #pragma unroll
        for (int j = 0; j < 8; j++)
            #pragma unroll
            for (int q = 0; q < 4; q++) acc[i][j][q] = 0.f;

    const int NT = K / 64;

    const uint32_t aBase = smem_u32(As);
    const uint32_t bBase = smem_u32(Bs);
    const uint32_t aoffElem = (uint32_t)((wm * 32 + (lane & 15)) * LDS + (lane >> 4) * 8);
    const uint32_t boffElem = (uint32_t)((wn * 64 + ((lane >> 4) << 3) + (lane & 7)) * LDS +
                                         ((lane >> 3) & 1) * 8);
    const uint32_t cpOff = (uint32_t)(crow * LDS + cseg * 8) * 2;

    auto issue = [&](int nit) {
        const int k0 = nit * 64;
        const int st = nit % NSTAGE;
        const uint32_t sa = aBase + st * STAGE_BYTES + cpOff;
        const uint32_t sb = bBase + st * STAGE_BYTES + cpOff;
        // B: cp.async (fp16 weights)
        const __half* gb = B + (size_t)(n0 + crow) * ldb + k0 + cseg * 8;
        #pragma unroll
        for (int i = 0; i < 4; i++) cp16(sb + i * 16, gb + i * 8);
        cp_commit();
        // A: fp32 LDG -> convert -> STS (32 elems/thread, 2 groups of 4xfloat4)
        const float* ga = A + (size_t)arow * lda + k0 + cseg * 8;
        #pragma unroll
        for (int grp = 0; grp < 2; grp++) {
            float4 f[4];
            #pragma unroll
            for (int i = 0; i < 4; i++)
                f[i] = *(const float4*)(ga + (grp * 4 + i) * 4);
            #pragma unroll
            for (int i = 0; i < 4; i++) {
                __half2 h0 = __floats2half2_rn(f[i].x, f[i].y);
                __half2 h1 = __floats2half2_rn(f[i].z, f[i].w);
                sts64(sa + (grp * 4 + i) * 8,
                      *(uint32_t*)&h0, *(uint32_t*)&h1);
            }
        }
    };

    issue(0);
    if (NT > 1) issue(1);

    for (int it = 0; it < NT; it++) {
        cp_wait<NSTAGE - 2>();
        __syncthreads();
        const int st = it % NSTAGE;
        const uint32_t aB = aBase + st * STAGE_BYTES;
        const uint32_t bB = bBase + st * STAGE_BYTES;
        GEMM_COMPUTE_STAGE(aB, bB)
        if (it + NSTAGE - 1 < NT) issue(it + NSTAGE - 1);
        else if (it + NSTAGE - 1 == NT) __syncthreads();  // protect last STS stage
    }

    GEMM_EPILOGUE()
}

// ---------------------------------------------------------------------------
// Aggregation (half2-vectorized, edge loop x8 then x1)
// ---------------------------------------------------------------------------
__device__ __forceinline__ float2 h2f2(const __half* p) {
    return __half22float2(*(const __half2*)p);
}

template <int F, int FPAD, bool OUT_F32>
__global__ void k_agg(const __half* __restrict__ h, const float* __restrict__ bias,
                      __half* __restrict__ out16, float* __restrict__ outf) {
    constexpr int F2 = F / 2;
    const int node = blockIdx.x;
    const int t = threadIdx.x;

    const float di = g_dinv[node];
    const int s0 = g_start[node];
    const int d  = g_deg[node];

    if (t < F2) {
        const int f = 2 * t;
        float2 a;
        {
            float2 v = h2f2(h + (size_t)node * F + f);
            float w = di * di;
            a.x = v.x * w; a.y = v.y * w;
        }
        int e = 0;
        for (; e + 8 <= d; e += 8) {
            int   s[8];
            float w[8];
            float2 v[8];
            #pragma unroll
            for (int u = 0; u < 8; u++) s[u] = g_csr_src[s0 + e + u];
            #pragma unroll
            for (int u = 0; u < 8; u++) w[u] = g_dinv[s[u]] * di;
            #pragma unroll
            for (int u = 0; u < 8; u++) v[u] = h2f2(h + (size_t)s[u] * F + f);
            #pragma unroll
            for (int u = 0; u < 8; u++) { a.x += v[u].x * w[u]; a.y += v[u].y * w[u]; }
        }
        for (; e < d; e++) {
            int s = g_csr_src[s0 + e];
            float w = g_dinv[s] * di;
            float2 v = h2f2(h + (size_t)s * F + f);
            a.x += v.x * w;
            a.y += v.y * w;
        }
        a.x += bias[f];
        a.y += bias[f + 1];
        a.x = a.x > 0.f ? a.x : 0.f;
        a.y = a.y > 0.f ? a.y : 0.f;
        if (OUT_F32) {
            outf[(size_t)node * F + f]     = a.x;
            outf[(size_t)node * F + f + 1] = a.y;
        } else {
            *(__half2*)(out16 + (size_t)node * FPAD + f) = __floats2half2_rn(a.x, a.y);
        }
    } else if (!OUT_F32 && t < FPAD / 2) {
        *(__half2*)(out16 + (size_t)node * FPAD + 2 * t) = __floats2half2_rn(0.f, 0.f);
    }
}

// ---------------------------------------------------------------------------
// Launch (R13 topology). Side stream: wt x3 [evW] -> CSR [evCSR].
// Main: wait(evW) -> GEMM1(fused cvt) -> wait(evCSR) -> agg1 -> L2 -> L3.
// ---------------------------------------------------------------------------
extern "C" void kernel_launch(void* const* d_in, const int* in_sizes, int n_in,
                              void* d_out, int out_size) {
    const float* x  = (const float*)d_in[0];
    const float* W1 = (const float*)d_in[1];
    const float* b1 = (const float*)d_in[2];
    const float* W2 = (const float*)d_in[3];
    const float* b2 = (const float*)d_in[4];
    const float* W3 = (const float*)d_in[5];
    const float* b3 = (const float*)d_in[6];
    const int*   ei = (const int*)d_in[7];   // int32 (JAX x64-disabled downcast)

    const int D0 = 1280;
    const int N = in_sizes[0] / D0;
    const int E = in_sizes[7] / 2;
    const int* src = ei;
    const int* dst = ei + E;

    __half *h16 = nullptr, *a16 = nullptr, *w1 = nullptr, *w2 = nullptr, *w3 = nullptr;
    cudaGetSymbolAddress((void**)&h16, g_h16);
    cudaGetSymbolAddress((void**)&a16, g_a16);
    cudaGetSymbolAddress((void**)&w1,  g_w1);
    cudaGetSymbolAddress((void**)&w2,  g_w2);
    cudaGetSymbolAddress((void**)&w3,  g_w3);

    static cudaStream_t s2 = nullptr;
    static cudaEvent_t evFork = nullptr, evW = nullptr, evCSR = nullptr;
    if (s2 == nullptr) {
        cudaStreamCreateWithFlags(&s2, cudaStreamNonBlocking);
        cudaEventCreateWithFlags(&evFork, cudaEventDisableTiming);
        cudaEventCreateWithFlags(&evW,    cudaEventDisableTiming);
        cudaEventCreateWithFlags(&evCSR,  cudaEventDisableTiming);
    }

    const int SMEM_BYTES = NSTAGE * STAGE_BYTES * 2;  // 110592
    cudaFuncSetAttribute(fp16_gemm, cudaFuncAttributeMaxDynamicSharedMemorySize,
                         SMEM_BYTES);
    cudaFuncSetAttribute(fp16_gemm_f32a, cudaFuncAttributeMaxDynamicSharedMemorySize,
                         SMEM_BYTES);

    const int T = 256;
    const int nbN = (N + T - 1) / T;
    const int nbE = (E + T - 1) / T;
    const int nbScan = (N + 255) / 256;
    const int ntm = MPAD / 128;  // 391

    // ---- fork side stream ----
    cudaEventRecord(evFork, 0);
    cudaStreamWaitEvent(s2, evFork, 0);

    // s2 phase 1: weight transposes
    k_wt<<<(512 * 1280 + 255) / 256, 256, 0, s2>>>(W1, w1, 1280, 512, 1280, 512);
    k_wt<<<(384 * 512 + 255) / 256, 256, 0, s2>>>(W2, w2, 512, 300, 512, 384);
    k_wt<<<(384 * 320 + 255) / 256, 256, 0, s2>>>(W3, w3, 300, 300, 320, 384);
    cudaEventRecord(evW, s2);

    // s2 phase 2: CSR build
    k_zero<<<nbN, T, 0, s2>>>(N);
    k_hist<<<nbE, T, 0, s2>>>(dst, E, N);
    k_scan_block<<<nbScan, 256, 0, s2>>>(N);
    k_scan_top<<<1, 256, 0, s2>>>(nbScan);
    k_finish<<<nbN, T, 0, s2>>>(N);
    k_fill<<<nbE, T, 0, s2>>>(src, dst, E, N);
    cudaEventRecord(evCSR, s2);

    // ---- Layer 1: GEMM reads fp32 x directly (fused conversion) ----
    cudaStreamWaitEvent(0, evW, 0);
    fp16_gemm_f32a<<<dim3(4, ntm), 256, SMEM_BYTES>>>(x, 1280, w1, 1280,
                                                      h16, N, 512, 1280);
    cudaStreamWaitEvent(0, evCSR, 0);
    k_agg<512, 512, false><<<N, 256>>>(h16, b1, a16, nullptr);

    // ---- Layer 2 ----
    fp16_gemm<<<dim3(3, ntm), 256, SMEM_BYTES>>>(a16, 512, w2, 512, h16, N, 300, 512);
    k_agg<300, 320, false><<<N, 160>>>(h16, b2, a16, nullptr);

    // ---- Layer 3 ----
    fp16_gemm<<<dim3(3, ntm), 256, SMEM_BYTES>>>(a16, 320, w3, 320, h16, N, 300, 320);
    k_agg<300, 320, true><<<N, 160>>>(h16, b3, nullptr, (float*)d_out);
}

// round 16
// speedup vs baseline: 1.0018x; 1.0018x over previous
#include <cuda_runtime.h>
#include <cuda_fp16.h>
#include <stdint.h>

// ---------------------------------------------------------------------------
// ProteinEncoder 3-layer GCN. fp16 mma.sync GEMM 128x128/BK64/3-stage.
// Layer-1 GEMM reads fp32 x directly (fused convert in A-load) -> k_cvt gone.
// h fp16. half2 CSR agg x8. R13 stream topology (prep on side stream).
// ---------------------------------------------------------------------------

#define MAX_N 50000
#define MPAD  50048            // 391 * 128
#define MAX_E 600000

__device__ __half g_h16[(size_t)MAX_N * 512];        // GEMM output (fp16)
__device__ __half g_a16[(size_t)MAX_N * 512];        // agg output (fp16, layers 2/3 input)
__device__ __half g_w1[512 * 1280];                  // W1^T [512,1280]
__device__ __half g_w2[384 * 512];                   // W2^T [384,512]
__device__ __half g_w3[384 * 320];                   // W3^T [384,320]

__device__ int   g_deg[MAX_N];
__device__ float g_dinv[MAX_N];
__device__ int   g_start[MAX_N];
__device__ int   g_scan[MAX_N];
__device__ int   g_cursor[MAX_N];
__device__ int   g_csr_src[MAX_E];
__device__ int   g_bsum[256];

// ---------------------------------------------------------------------------
// helpers
// ---------------------------------------------------------------------------
__device__ __forceinline__ uint32_t smem_u32(const void* p) {
    uint32_t r;
    asm("{ .reg .u64 t; cvta.to.shared.u64 t, %1; cvt.u32.u64 %0, t; }"
        : "=r"(r) : "l"(p));
    return r;
}
__device__ __forceinline__ void ldsm4(uint32_t& r0, uint32_t& r1, uint32_t& r2,
                                      uint32_t& r3, uint32_t addr) {
    asm volatile("ldmatrix.sync.aligned.m8n8.x4.shared.b16 {%0,%1,%2,%3}, [%4];"
                 : "=r"(r0), "=r"(r1), "=r"(r2), "=r"(r3) : "r"(addr));
}
__device__ __forceinline__ void mma16816(float* c, const uint32_t* a,
                                         uint32_t b0, uint32_t b1) {
    asm volatile(
        "mma.sync.aligned.m16n8k16.row.col.f32.f16.f16.f32 "
        "{%0,%1,%2,%3}, {%4,%5,%6,%7}, {%8,%9}, {%0,%1,%2,%3};"
        : "+f"(c[0]), "+f"(c[1]), "+f"(c[2]), "+f"(c[3])
        : "r"(a[0]), "r"(a[1]), "r"(a[2]), "r"(a[3]), "r"(b0), "r"(b1));
}
__device__ __forceinline__ void cp16(uint32_t smem, const void* gmem) {
    asm volatile("cp.async.cg.shared.global [%0], [%1], 16;"
                 :: "r"(smem), "l"(gmem));
}
__device__ __forceinline__ void cp_commit() {
    asm volatile("cp.async.commit_group;" ::: "memory");
}
template <int NN>
__device__ __forceinline__ void cp_wait() {
    asm volatile("cp.async.wait_group %0;" :: "n"(NN) : "memory");
}
__device__ __forceinline__ void sts64(uint32_t addr, uint32_t v0, uint32_t v1) {
    asm volatile("st.shared.v2.b32 [%0], {%1,%2};" :: "r"(addr), "r"(v0), "r"(v1)
                 : "memory");
}

// ---------------------------------------------------------------------------
// CSR build
// ---------------------------------------------------------------------------
__global__ void k_zero(int n) {
    int i = blockIdx.x * blockDim.x + threadIdx.x;
    if (i < n) { g_deg[i] = 0; g_cursor[i] = 0; }
}
__global__ void k_hist(const int* __restrict__ dst, int E, int n) {
    int e = blockIdx.x * blockDim.x + threadIdx.x;
    if (e < E) {
        int d = dst[e];
        if (d >= 0 && d < n) atomicAdd(&g_deg[d], 1);
    }
}
__global__ void k_scan_block(int n) {
    __shared__ int sh[256];
    int t = threadIdx.x;
    int i = blockIdx.x * 256 + t;
    int v = (i < n) ? g_deg[i] : 0;
    sh[t] = v;
    __syncthreads();
    #pragma unroll
    for (int off = 1; off < 256; off <<= 1) {
        int x = (t >= off) ? sh[t - off] : 0;
        __syncthreads();
        sh[t] += x;
        __syncthreads();
    }
    if (i < n) g_scan[i] = sh[t];
    if (t == 255) g_bsum[blockIdx.x] = sh[255];
}
__global__ void k_scan_top(int nb) {
    __shared__ int sh[256];
    int t = threadIdx.x;
    int v = (t < nb) ? g_bsum[t] : 0;
    sh[t] = v;
    __syncthreads();
    #pragma unroll
    for (int off = 1; off < 256; off <<= 1) {
        int x = (t >= off) ? sh[t - off] : 0;
        __syncthreads();
        sh[t] += x;
        __syncthreads();
    }
    if (t < nb) g_bsum[t] = sh[t] - v;
}
__global__ void k_finish(int n) {
    int i = blockIdx.x * blockDim.x + threadIdx.x;
    if (i < n) {
        g_start[i] = g_scan[i] - g_deg[i] + g_bsum[i >> 8];
        g_dinv[i]  = rsqrtf((float)(g_deg[i] + 1));
    }
}
__global__ void k_fill(const int* __restrict__ src,
                       const int* __restrict__ dst, int E, int n) {
    int e = blockIdx.x * blockDim.x + threadIdx.x;
    if (e < E) {
        int d = dst[e];
        int s = src[e];
        if (d >= 0 && d < n && s >= 0 && s < n) {
            int p = atomicAdd(&g_cursor[d], 1);
            g_csr_src[g_start[d] + p] = s;
        }
    }
}

// W [K,N] fp32 -> W^T [Npad,Kpad] fp16, zero-padded
__global__ void k_wt(const float* __restrict__ W, __half* __restrict__ wt,
                     int K, int N, int Kpad, int Npad) {
    int idx = blockIdx.x * blockDim.x + threadIdx.x;
    if (idx < Npad * Kpad) {
        int n = idx / Kpad, k = idx - n * Kpad;
        float v = (n < N && k < K) ? W[(size_t)k * N + n] : 0.f;
        wt[idx] = __float2half_rn(v);
    }
}

// ---------------------------------------------------------------------------
// GEMM common geometry: 128x128 CTA, BK=64, 3 stages, 256 threads (8 warps
// 4x2, warp tile 32x64). Proven config (R9: 272us layer1, tensor 40%).
// ---------------------------------------------------------------------------
#define LDS 72
#define STAGE_ELEMS (128 * LDS)
#define STAGE_BYTES (STAGE_ELEMS * 2)
#define NSTAGE 3

// inner mainloop body shared by both variants (macro to keep identical SASS)
#define GEMM_COMPUTE_STAGE(aB, bB)                                             \
    _Pragma("unroll")                                                          \
    for (int ks = 0; ks < 4; ks++) {                                           \
        const uint32_t kofs = (uint32_t)(ks * 16) * 2;                         \
        uint32_t a[2][4];                                                      \
        _Pragma("unroll")                                                      \
        for (int mi = 0; mi < 2; mi++)                                         \
            ldsm4(a[mi][0], a[mi][1], a[mi][2], a[mi][3],                      \
                  (aB) + (aoffElem + (uint32_t)(mi * 16) * LDS) * 2 + kofs);   \
        uint32_t b[4][4];                                                      \
        _Pragma("unroll")                                                      \
        for (int nb = 0; nb < 4; nb++)                                         \
            ldsm4(b[nb][0], b[nb][1], b[nb][2], b[nb][3],                      \
                  (bB) + (boffElem + (uint32_t)(nb * 16) * LDS) * 2 + kofs);   \
        _Pragma("unroll")                                                      \
        for (int mi = 0; mi < 2; mi++)                                         \
            _Pragma("unroll")                                                  \
            for (int nb = 0; nb < 4; nb++) {                                   \
                mma16816(acc[mi][nb * 2 + 0], a[mi], b[nb][0], b[nb][1]);      \
                mma16816(acc[mi][nb * 2 + 1], a[mi], b[nb][2], b[nb][3]);      \
            }                                                                  \
    }

#define GEMM_EPILOGUE()                                                        \
    const int g = lane >> 2, tg = lane & 3;                                    \
    _Pragma("unroll")                                                          \
    for (int mi = 0; mi < 2; mi++) {                                           \
        _Pragma("unroll")                                                      \
        for (int nj = 0; nj < 8; nj++) {                                       \
            int col = n0 + wn * 64 + nj * 8 + tg * 2;                          \
            int mrow = m0 + wm * 32 + mi * 16 + g;                             \
            _Pragma("unroll")                                                  \
            for (int hf = 0; hf < 2; hf++) {                                   \
                int r = mrow + hf * 8;                                         \
                if (r < M && col + 2 <= Nout) {                                \
                    __half2 v = __floats2half2_rn(acc[mi][nj][hf * 2 + 0],     \
                                                  acc[mi][nj][hf * 2 + 1]);    \
                    *(__half2*)(C + (size_t)r * Nout + col) = v;               \
                }                                                              \
            }                                                                  \
        }                                                                      \
    }

// ---- variant A: fp16 A via cp.async (layers 2/3) ----
__global__ __launch_bounds__(256) void fp16_gemm(
    const __half* __restrict__ A, int lda,
    const __half* __restrict__ B, int ldb,
    __half* __restrict__ C, int M, int Nout, int K) {
    extern __shared__ __half sm[];
    __half* As = sm;
    __half* Bs = sm + NSTAGE * STAGE_ELEMS;

    const int tid = threadIdx.x;
    const int lane = tid & 31;
    const int wid = tid >> 5;
    const int wm = wid >> 1;
    const int wn = wid & 1;
    const int m0 = blockIdx.y * 128;
    const int n0 = blockIdx.x * 128;

    const int crow = tid >> 1;
    const int cseg = (tid & 1) * 4;

    float acc[2][8][4];
    #pragma unroll
    for (int i = 0; i < 2; i++)
        #pragma unroll
        for (int j = 0; j < 8; j++)
            #pragma unroll
            for (int q = 0; q < 4; q++) acc[i][j][q] = 0.f;

    const int NT = K / 64;

    const uint32_t aBase = smem_u32(As);
    const uint32_t bBase = smem_u32(Bs);
    const uint32_t aoffElem = (uint32_t)((wm * 32 + (lane & 15)) * LDS + (lane >> 4) * 8);
    const uint32_t boffElem = (uint32_t)((wn * 64 + ((lane >> 4) << 3) + (lane & 7)) * LDS +
                                         ((lane >> 3) & 1) * 8);
    const uint32_t cpOff = (uint32_t)(crow * LDS + cseg * 8) * 2;

    auto issue = [&](int nit) {
        const int k0 = nit * 64;
        const int st = nit % NSTAGE;
        const uint32_t sa = aBase + st * STAGE_BYTES + cpOff;
        const uint32_t sb = bBase + st * STAGE_BYTES + cpOff;
        const __half* ga = A + (size_t)(m0 + crow) * lda + k0 + cseg * 8;
        const __half* gb = B + (size_t)(n0 + crow) * ldb + k0 + cseg * 8;
        #pragma unroll
        for (int i = 0; i < 4; i++) cp16(sa + i * 16, ga + i * 8);
        #pragma unroll
        for (int i = 0; i < 4; i++) cp16(sb + i * 16, gb + i * 8);
        cp_commit();
    };

    issue(0);
    if (NT > 1) issue(1);

    for (int it = 0; it < NT; it++) {
        cp_wait<NSTAGE - 2>();
        __syncthreads();
        const int st = it % NSTAGE;
        const uint32_t aB = aBase + st * STAGE_BYTES;
        const uint32_t bB = bBase + st * STAGE_BYTES;
        GEMM_COMPUTE_STAGE(aB, bB)
        if (it + NSTAGE - 1 < NT) issue(it + NSTAGE - 1);
    }

    GEMM_EPILOGUE()
}

// ---- variant B: fp32 A with fused convert (layer 1; A = raw x) ----
__global__ __launch_bounds__(256) void fp16_gemm_f32a(
    const float* __restrict__ A, int lda,
    const __half* __restrict__ B, int ldb,
    __half* __restrict__ C, int M, int Nout, int K) {
    extern __shared__ __half sm[];
    __half* As = sm;
    __half* Bs = sm + NSTAGE * STAGE_ELEMS;

    const int tid = threadIdx.x;
    const int lane = tid & 31;
    const int wid = tid >> 5;
    const int wm = wid >> 1;
    const int wn = wid & 1;
    const int m0 = blockIdx.y * 128;
    const int n0 = blockIdx.x * 128;

    const int crow = tid >> 1;
    const int cseg = (tid & 1) * 4;

    // clamp pad rows (m0+crow may exceed M-1 on the last tile; x has no pad)
    int arow = m0 + crow;
    if (arow > M - 1) arow = M - 1;

    float acc[2][8][4];
    #pragma unroll
    for (int i = 0; i < 2; i++)
        #pragma unroll
        for (int j = 0; j < 8; j++)
            #pragma unroll
            for (int q = 0; q < 4; q++) acc[i][j][q] = 0.f;

    const int NT = K / 64;

    const uint32_t aBase = smem_u32(As);
    const uint32_t bBase = smem_u32(Bs);
    const uint32_t aoffElem = (uint32_t)((wm * 32 + (lane & 15)) * LDS + (lane >> 4) * 8);
    const uint32_t boffElem = (uint32_t)((wn * 64 + ((lane >> 4) << 3) + (lane & 7)) * LDS +
                                         ((lane >> 3) & 1) * 8);
    const uint32_t cpOff = (uint32_t)(crow * LDS + cseg * 8) * 2;

    auto issue = [&](int nit) {
        const int k0 = nit * 64;
        const int st = nit % NSTAGE;
        const uint32_t sa = aBase + st * STAGE_BYTES + cpOff;
        const uint32_t sb = bBase + st * STAGE_BYTES + cpOff;
        // B: cp.async (fp16 weights)
        const __half* gb = B + (size_t)(n0 + crow) * ldb + k0 + cseg * 8;
        #pragma unroll
        for (int i = 0; i < 4; i++) cp16(sb + i * 16, gb + i * 8);
        cp_commit();
        // A: fp32 LDG -> convert -> STS (32 elems/thread, 2 groups of 4xfloat4)
        const float* ga = A + (size_t)arow * lda + k0 + cseg * 8;
        #pragma unroll
        for (int grp = 0; grp < 2; grp++) {
            float4 f[4];
            #pragma unroll
            for (int i = 0; i < 4; i++)
                f[i] = *(const float4*)(ga + (grp * 4 + i) * 4);
            #pragma unroll
            for (int i = 0; i < 4; i++) {
                __half2 h0 = __floats2half2_rn(f[i].x, f[i].y);
                __half2 h1 = __floats2half2_rn(f[i].z, f[i].w);
                sts64(sa + (grp * 4 + i) * 8,
                      *(uint32_t*)&h0, *(uint32_t*)&h1);
            }
        }
    };

    issue(0);
    if (NT > 1) issue(1);

    for (int it = 0; it < NT; it++) {
        cp_wait<NSTAGE - 2>();
        __syncthreads();
        const int st = it % NSTAGE;
        const uint32_t aB = aBase + st * STAGE_BYTES;
        const uint32_t bB = bBase + st * STAGE_BYTES;
        GEMM_COMPUTE_STAGE(aB, bB)
        if (it + NSTAGE - 1 < NT) issue(it + NSTAGE - 1);
        else if (it + NSTAGE - 1 == NT) __syncthreads();  // protect last STS stage
    }

    GEMM_EPILOGUE()
}

// ---------------------------------------------------------------------------
// Aggregation (half2-vectorized, edge loop x8 then x1)
// ---------------------------------------------------------------------------
__device__ __forceinline__ float2 h2f2(const __half* p) {
    return __half22float2(*(const __half2*)p);
}

template <int F, int FPAD, bool OUT_F32>
__global__ void k_agg(const __half* __restrict__ h, const float* __restrict__ bias,
                      __half* __restrict__ out16, float* __restrict__ outf) {
    constexpr int F2 = F / 2;
    const int node = blockIdx.x;
    const int t = threadIdx.x;

    const float di = g_dinv[node];
    const int s0 = g_start[node];
    const int d  = g_deg[node];

    if (t < F2) {
        const int f = 2 * t;
        float2 a;
        {
            float2 v = h2f2(h + (size_t)node * F + f);
            float w = di * di;
            a.x = v.x * w; a.y = v.y * w;
        }
        int e = 0;
        for (; e + 8 <= d; e += 8) {
            int   s[8];
            float w[8];
            float2 v[8];
            #pragma unroll
            for (int u = 0; u < 8; u++) s[u] = g_csr_src[s0 + e + u];
            #pragma unroll
            for (int u = 0; u < 8; u++) w[u] = g_dinv[s[u]] * di;
            #pragma unroll
            for (int u = 0; u < 8; u++) v[u] = h2f2(h + (size_t)s[u] * F + f);
            #pragma unroll
            for (int u = 0; u < 8; u++) { a.x += v[u].x * w[u]; a.y += v[u].y * w[u]; }
        }
        for (; e < d; e++) {
            int s = g_csr_src[s0 + e];
            float w = g_dinv[s] * di;
            float2 v = h2f2(h + (size_t)s * F + f);
            a.x += v.x * w;
            a.y += v.y * w;
        }
        a.x += bias[f];
        a.y += bias[f + 1];
        a.x = a.x > 0.f ? a.x : 0.f;
        a.y = a.y > 0.f ? a.y : 0.f;
        if (OUT_F32) {
            outf[(size_t)node * F + f]     = a.x;
            outf[(size_t)node * F + f + 1] = a.y;
        } else {
            *(__half2*)(out16 + (size_t)node * FPAD + f) = __floats2half2_rn(a.x, a.y);
        }
    } else if (!OUT_F32 && t < FPAD / 2) {
        *(__half2*)(out16 + (size_t)node * FPAD + 2 * t) = __floats2half2_rn(0.f, 0.f);
    }
}

// ---------------------------------------------------------------------------
// Launch (R13 topology). Side stream: wt x3 [evW] -> CSR [evCSR].
// Main: wait(evW) -> GEMM1(fused cvt) -> wait(evCSR) -> agg1 -> L2 -> L3.
// ---------------------------------------------------------------------------
extern "C" void kernel_launch(void* const* d_in, const int* in_sizes, int n_in,
                              void* d_out, int out_size) {
    const float* x  = (const float*)d_in[0];
    const float* W1 = (const float*)d_in[1];
    const float* b1 = (const float*)d_in[2];
    const float* W2 = (const float*)d_in[3];
    const float* b2 = (const float*)d_in[4];
    const float* W3 = (const float*)d_in[5];
    const float* b3 = (const float*)d_in[6];
    const int*   ei = (const int*)d_in[7];   // int32 (JAX x64-disabled downcast)

    const int D0 = 1280;
    const int N = in_sizes[0] / D0;
    const int E = in_sizes[7] / 2;
    const int* src = ei;
    const int* dst = ei + E;

    __half *h16 = nullptr, *a16 = nullptr, *w1 = nullptr, *w2 = nullptr, *w3 = nullptr;
    cudaGetSymbolAddress((void**)&h16, g_h16);
    cudaGetSymbolAddress((void**)&a16, g_a16);
    cudaGetSymbolAddress((void**)&w1,  g_w1);
    cudaGetSymbolAddress((void**)&w2,  g_w2);
    cudaGetSymbolAddress((void**)&w3,  g_w3);

    static cudaStream_t s2 = nullptr;
    static cudaEvent_t evFork = nullptr, evW = nullptr, evCSR = nullptr;
    if (s2 == nullptr) {
        cudaStreamCreateWithFlags(&s2, cudaStreamNonBlocking);
        cudaEventCreateWithFlags(&evFork, cudaEventDisableTiming);
        cudaEventCreateWithFlags(&evW,    cudaEventDisableTiming);
        cudaEventCreateWithFlags(&evCSR,  cudaEventDisableTiming);
    }

    const int SMEM_BYTES = NSTAGE * STAGE_BYTES * 2;  // 110592
    cudaFuncSetAttribute(fp16_gemm, cudaFuncAttributeMaxDynamicSharedMemorySize,
                         SMEM_BYTES);
    cudaFuncSetAttribute(fp16_gemm_f32a, cudaFuncAttributeMaxDynamicSharedMemorySize,
                         SMEM_BYTES);

    const int T = 256;
    const int nbN = (N + T - 1) / T;
    const int nbE = (E + T - 1) / T;
    const int nbScan = (N + 255) / 256;
    const int ntm = MPAD / 128;  // 391

    // ---- fork side stream ----
    cudaEventRecord(evFork, 0);
    cudaStreamWaitEvent(s2, evFork, 0);

    // s2 phase 1: weight transposes
    k_wt<<<(512 * 1280 + 255) / 256, 256, 0, s2>>>(W1, w1, 1280, 512, 1280, 512);
    k_wt<<<(384 * 512 + 255) / 256, 256, 0, s2>>>(W2, w2, 512, 300, 512, 384);
    k_wt<<<(384 * 320 + 255) / 256, 256, 0, s2>>>(W3, w3, 300, 300, 320, 384);
    cudaEventRecord(evW, s2);

    // s2 phase 2: CSR build
    k_zero<<<nbN, T, 0, s2>>>(N);
    k_hist<<<nbE, T, 0, s2>>>(dst, E, N);
    k_scan_block<<<nbScan, 256, 0, s2>>>(N);
    k_scan_top<<<1, 256, 0, s2>>>(nbScan);
    k_finish<<<nbN, T, 0, s2>>>(N);
    k_fill<<<nbE, T, 0, s2>>>(src, dst, E, N);
    cudaEventRecord(evCSR, s2);

    // ---- Layer 1: GEMM reads fp32 x directly (fused conversion) ----
    cudaStreamWaitEvent(0, evW, 0);
    fp16_gemm_f32a<<<dim3(4, ntm), 256, SMEM_BYTES>>>(x, 1280, w1, 1280,
                                                      h16, N, 512, 1280);
    cudaStreamWaitEvent(0, evCSR, 0);
    k_agg<512, 512, false><<<N, 256>>>(h16, b1, a16, nullptr);

    // ---- Layer 2 ----
    fp16_gemm<<<dim3(3, ntm), 256, SMEM_BYTES>>>(a16, 512, w2, 512, h16, N, 300, 512);
    k_agg<300, 320, false><<<N, 160>>>(h16, b2, a16, nullptr);

    // ---- Layer 3 ----
    fp16_gemm<<<dim3(3, ntm), 256, SMEM_BYTES>>>(a16, 320, w3, 320, h16, N, 300, 320);
    k_agg<300, 320, true><<<N, 160>>>(h16, b3, nullptr, (float*)d_out);
}

// round 17
// speedup vs baseline: 1.3859x; 1.3834x over previous
#include <cuda_runtime.h>
#include <cuda_fp16.h>
#include <stdint.h>

// ---------------------------------------------------------------------------
// ProteinEncoder 3-layer GCN. fp16 mma.sync GEMM 128x128/BK64/3-stage (R9/R13
// proven). h fp16. CSR agg vectorized to 4 features/thread (uint2 loads).
// R13 stream topology: side stream wt x3 [evW] -> CSR [evCSR]; main stream
// cvt -> wait(evW) -> GEMM1 -> wait(evCSR) -> agg1 -> L2 -> L3.
// ---------------------------------------------------------------------------

#define MAX_N 50000
#define MPAD  50048            // 391 * 128
#define MAX_E 600000

__device__ __half g_h16[(size_t)MAX_N * 512];        // GEMM output (fp16)
__device__ __half g_a16[(size_t)MPAD * 1280];        // GEMM A input (fp16)
__device__ __half g_w1[512 * 1280];                  // W1^T [512,1280]
__device__ __half g_w2[384 * 512];                   // W2^T [384,512]
__device__ __half g_w3[384 * 320];                   // W3^T [384,320]

__device__ int   g_deg[MAX_N];
__device__ float g_dinv[MAX_N];
__device__ int   g_start[MAX_N];
__device__ int   g_scan[MAX_N];
__device__ int   g_cursor[MAX_N];
__device__ int   g_csr_src[MAX_E];
__device__ int   g_bsum[256];

// ---------------------------------------------------------------------------
// helpers
// ---------------------------------------------------------------------------
__device__ __forceinline__ uint32_t smem_u32(const void* p) {
    uint32_t r;
    asm("{ .reg .u64 t; cvta.to.shared.u64 t, %1; cvt.u32.u64 %0, t; }"
        : "=r"(r) : "l"(p));
    return r;
}
__device__ __forceinline__ void ldsm4(uint32_t& r0, uint32_t& r1, uint32_t& r2,
                                      uint32_t& r3, uint32_t addr) {
    asm volatile("ldmatrix.sync.aligned.m8n8.x4.shared.b16 {%0,%1,%2,%3}, [%4];"
                 : "=r"(r0), "=r"(r1), "=r"(r2), "=r"(r3) : "r"(addr));
}
__device__ __forceinline__ void mma16816(float* c, const uint32_t* a,
                                         uint32_t b0, uint32_t b1) {
    asm volatile(
        "mma.sync.aligned.m16n8k16.row.col.f32.f16.f16.f32 "
        "{%0,%1,%2,%3}, {%4,%5,%6,%7}, {%8,%9}, {%0,%1,%2,%3};"
        : "+f"(c[0]), "+f"(c[1]), "+f"(c[2]), "+f"(c[3])
        : "r"(a[0]), "r"(a[1]), "r"(a[2]), "r"(a[3]), "r"(b0), "r"(b1));
}
__device__ __forceinline__ void cp16(uint32_t smem, const void* gmem) {
    asm volatile("cp.async.cg.shared.global [%0], [%1], 16;"
                 :: "r"(smem), "l"(gmem));
}
__device__ __forceinline__ void cp_commit() {
    asm volatile("cp.async.commit_group;" ::: "memory");
}
template <int NN>
__device__ __forceinline__ void cp_wait() {
    asm volatile("cp.async.wait_group %0;" :: "n"(NN) : "memory");
}

// ---------------------------------------------------------------------------
// CSR build
// ---------------------------------------------------------------------------
__global__ void k_zero(int n) {
    int i = blockIdx.x * blockDim.x + threadIdx.x;
    if (i < n) { g_deg[i] = 0; g_cursor[i] = 0; }
}
__global__ void k_hist(const int* __restrict__ dst, int E, int n) {
    int e = blockIdx.x * blockDim.x + threadIdx.x;
    if (e < E) {
        int d = dst[e];
        if (d >= 0 && d < n) atomicAdd(&g_deg[d], 1);
    }
}
__global__ void k_scan_block(int n) {
    __shared__ int sh[256];
    int t = threadIdx.x;
    int i = blockIdx.x * 256 + t;
    int v = (i < n) ? g_deg[i] : 0;
    sh[t] = v;
    __syncthreads();
    #pragma unroll
    for (int off = 1; off < 256; off <<= 1) {
        int x = (t >= off) ? sh[t - off] : 0;
        __syncthreads();
        sh[t] += x;
        __syncthreads();
    }
    if (i < n) g_scan[i] = sh[t];
    if (t == 255) g_bsum[blockIdx.x] = sh[255];
}
__global__ void k_scan_top(int nb) {
    __shared__ int sh[256];
    int t = threadIdx.x;
    int v = (t < nb) ? g_bsum[t] : 0;
    sh[t] = v;
    __syncthreads();
    #pragma unroll
    for (int off = 1; off < 256; off <<= 1) {
        int x = (t >= off) ? sh[t - off] : 0;
        __syncthreads();
        sh[t] += x;
        __syncthreads();
    }
    if (t < nb) g_bsum[t] = sh[t] - v;
}
__global__ void k_finish(int n) {
    int i = blockIdx.x * blockDim.x + threadIdx.x;
    if (i < n) {
        g_start[i] = g_scan[i] - g_deg[i] + g_bsum[i >> 8];
        g_dinv[i]  = rsqrtf((float)(g_deg[i] + 1));
    }
}
__global__ void k_fill(const int* __restrict__ src,
                       const int* __restrict__ dst, int E, int n) {
    int e = blockIdx.x * blockDim.x + threadIdx.x;
    if (e < E) {
        int d = dst[e];
        int s = src[e];
        if (d >= 0 && d < n && s >= 0 && s < n) {
            int p = atomicAdd(&g_cursor[d], 1);
            g_csr_src[g_start[d] + p] = s;
        }
    }
}

// ---------------------------------------------------------------------------
// conversions
// ---------------------------------------------------------------------------
__global__ void k_cvt(const float* __restrict__ x, __half* __restrict__ a16,
                      int total) {
    int i = (blockIdx.x * blockDim.x + threadIdx.x) * 4;
    if (i + 4 <= total) {
        float4 v = *(const float4*)(x + i);
        *(__half2*)(a16 + i)     = __floats2half2_rn(v.x, v.y);
        *(__half2*)(a16 + i + 2) = __floats2half2_rn(v.z, v.w);
    }
}
// W [K,N] fp32 -> W^T [Npad,Kpad] fp16, zero-padded
__global__ void k_wt(const float* __restrict__ W, __half* __restrict__ wt,
                     int K, int N, int Kpad, int Npad) {
    int idx = blockIdx.x * blockDim.x + threadIdx.x;
    if (idx < Npad * Kpad) {
        int n = idx / Kpad, k = idx - n * Kpad;
        float v = (n < N && k < K) ? W[(size_t)k * N + n] : 0.f;
        wt[idx] = __float2half_rn(v);
    }
}

// ---------------------------------------------------------------------------
// fp16 single-pass GEMM, cp.async 3-stage, BK=64 (R13 proven config).
// grid (ntilesN, 391), 256 threads (8 warps, 4x2, warp tile 32x64).
// ---------------------------------------------------------------------------
#define LDS 72
#define STAGE_ELEMS (128 * LDS)
#define STAGE_BYTES (STAGE_ELEMS * 2)
#define NSTAGE 3

__global__ __launch_bounds__(256) void fp16_gemm(
    const __half* __restrict__ A, int lda,
    const __half* __restrict__ B, int ldb,
    __half* __restrict__ C, int M, int Nout, int K) {
    extern __shared__ __half sm[];
    __half* As = sm;
    __half* Bs = sm + NSTAGE * STAGE_ELEMS;

    const int tid = threadIdx.x;
    const int lane = tid & 31;
    const int wid = tid >> 5;
    const int wm = wid >> 1;
    const int wn = wid & 1;
    const int m0 = blockIdx.y * 128;
    const int n0 = blockIdx.x * 128;

    const int crow = tid >> 1;
    const int cseg = (tid & 1) * 4;

    float acc[2][8][4];
    #pragma unroll
    for (int i = 0; i < 2; i++)
        #pragma unroll
        for (int j = 0; j < 8; j++)
            #pragma unroll
            for (int q = 0; q < 4; q++) acc[i][j][q] = 0.f;

    const int NT = K / 64;

    const uint32_t aBase = smem_u32(As);
    const uint32_t bBase = smem_u32(Bs);
    const uint32_t aoffElem = (uint32_t)((wm * 32 + (lane & 15)) * LDS + (lane >> 4) * 8);
    const uint32_t boffElem = (uint32_t)((wn * 64 + ((lane >> 4) << 3) + (lane & 7)) * LDS +
                                         ((lane >> 3) & 1) * 8);
    const uint32_t cpOff = (uint32_t)(crow * LDS + cseg * 8) * 2;

    auto issue = [&](int nit) {
        const int k0 = nit * 64;
        const int st = nit % NSTAGE;
        const uint32_t sa = aBase + st * STAGE_BYTES + cpOff;
        const uint32_t sb = bBase + st * STAGE_BYTES + cpOff;
        const __half* ga = A + (size_t)(m0 + crow) * lda + k0 + cseg * 8;
        const __half* gb = B + (size_t)(n0 + crow) * ldb + k0 + cseg * 8;
        #pragma unroll
        for (int i = 0; i < 4; i++) cp16(sa + i * 16, ga + i * 8);
        #pragma unroll
        for (int i = 0; i < 4; i++) cp16(sb + i * 16, gb + i * 8);
        cp_commit();
    };

    issue(0);
    if (NT > 1) issue(1);

    for (int it = 0; it < NT; it++) {
        cp_wait<NSTAGE - 2>();
        __syncthreads();

        const int st = it % NSTAGE;
        const uint32_t aB = aBase + st * STAGE_BYTES;
        const uint32_t bB = bBase + st * STAGE_BYTES;

        #pragma unroll
        for (int ks = 0; ks < 4; ks++) {
            const uint32_t kofs = (uint32_t)(ks * 16) * 2;
            uint32_t a[2][4];
            #pragma unroll
            for (int mi = 0; mi < 2; mi++)
                ldsm4(a[mi][0], a[mi][1], a[mi][2], a[mi][3],
                      aB + (aoffElem + (uint32_t)(mi * 16) * LDS) * 2 + kofs);
            uint32_t b[4][4];
            #pragma unroll
            for (int nb = 0; nb < 4; nb++)
                ldsm4(b[nb][0], b[nb][1], b[nb][2], b[nb][3],
                      bB + (boffElem + (uint32_t)(nb * 16) * LDS) * 2 + kofs);
            #pragma unroll
            for (int mi = 0; mi < 2; mi++)
                #pragma unroll
                for (int nb = 0; nb < 4; nb++) {
                    mma16816(acc[mi][nb * 2 + 0], a[mi], b[nb][0], b[nb][1]);
                    mma16816(acc[mi][nb * 2 + 1], a[mi], b[nb][2], b[nb][3]);
                }
        }

        if (it + NSTAGE - 1 < NT) issue(it + NSTAGE - 1);
    }

    const int g = lane >> 2, tg = lane & 3;
    #pragma unroll
    for (int mi = 0; mi < 2; mi++) {
        #pragma unroll
        for (int nj = 0; nj < 8; nj++) {
            int col = n0 + wn * 64 + nj * 8 + tg * 2;
            int mrow = m0 + wm * 32 + mi * 16 + g;
            #pragma unroll
            for (int half = 0; half < 2; half++) {
                int r = mrow + half * 8;
                if (r < M && col + 2 <= Nout) {
                    __half2 v = __floats2half2_rn(acc[mi][nj][half * 2 + 0],
                                                  acc[mi][nj][half * 2 + 1]);
                    *(__half2*)(C + (size_t)r * Nout + col) = v;
                }
            }
        }
    }
}

// ---------------------------------------------------------------------------
// Aggregation: 4 features/thread via uint2 (8B) loads, edge loop x8.
//   F=512: 128 threads (t<128 work). F=300: 96 threads (t<75 work, t<80 pad).
// ---------------------------------------------------------------------------
__device__ __forceinline__ float4 h4f4(const __half* p) {
    uint2 u = *(const uint2*)p;
    float2 fa = __half22float2(*(__half2*)&u.x);
    float2 fb = __half22float2(*(__half2*)&u.y);
    return make_float4(fa.x, fa.y, fb.x, fb.y);
}

template <int F, int FPAD, bool OUT_F32>
__global__ void k_agg4(const __half* __restrict__ h, const float* __restrict__ bias,
                       __half* __restrict__ out16, float* __restrict__ outf) {
    constexpr int F4 = F / 4;          // 128 for F=512, 75 for F=300
    const int node = blockIdx.x;
    const int t = threadIdx.x;

    const float di = g_dinv[node];
    const int s0 = g_start[node];
    const int d  = g_deg[node];

    if (t < F4) {
        const int f = 4 * t;
        float4 a;
        {
            float4 v = h4f4(h + (size_t)node * F + f);
            float w = di * di;
            a.x = v.x * w; a.y = v.y * w; a.z = v.z * w; a.w = v.w * w;
        }
        int e = 0;
        for (; e + 8 <= d; e += 8) {
            int    s[8];
            float  w[8];
            float4 v[8];
            #pragma unroll
            for (int u = 0; u < 8; u++) s[u] = g_csr_src[s0 + e + u];
            #pragma unroll
            for (int u = 0; u < 8; u++) w[u] = g_dinv[s[u]] * di;
            #pragma unroll
            for (int u = 0; u < 8; u++) v[u] = h4f4(h + (size_t)s[u] * F + f);
            #pragma unroll
            for (int u = 0; u < 8; u++) {
                a.x += v[u].x * w[u]; a.y += v[u].y * w[u];
                a.z += v[u].z * w[u]; a.w += v[u].w * w[u];
            }
        }
        for (; e < d; e++) {
            int s = g_csr_src[s0 + e];
            float w = g_dinv[s] * di;
            float4 v = h4f4(h + (size_t)s * F + f);
            a.x += v.x * w; a.y += v.y * w; a.z += v.z * w; a.w += v.w * w;
        }
        float4 b = *(const float4*)(bias + f);
        a.x += b.x; a.y += b.y; a.z += b.z; a.w += b.w;
        a.x = a.x > 0.f ? a.x : 0.f;
        a.y = a.y > 0.f ? a.y : 0.f;
        a.z = a.z > 0.f ? a.z : 0.f;
        a.w = a.w > 0.f ? a.w : 0.f;
        if (OUT_F32) {
            *(float4*)(outf + (size_t)node * F + f) = a;
        } else {
            __half2 h0 = __floats2half2_rn(a.x, a.y);
            __half2 h1 = __floats2half2_rn(a.z, a.w);
            uint2 u;
            u.x = *(uint32_t*)&h0;
            u.y = *(uint32_t*)&h1;
            *(uint2*)(out16 + (size_t)node * FPAD + f) = u;
        }
    } else if (!OUT_F32 && t < FPAD / 4) {
        uint2 z = make_uint2(0u, 0u);
        *(uint2*)(out16 + (size_t)node * FPAD + 4 * t) = z;
    }
}

// ---------------------------------------------------------------------------
// Launch (R13 topology). Side stream: wt x3 [evW] -> CSR [evCSR].
// Main: cvt -> wait(evW) -> GEMM1 -> wait(evCSR) -> agg1 -> L2 -> L3.
// ---------------------------------------------------------------------------
extern "C" void kernel_launch(void* const* d_in, const int* in_sizes, int n_in,
                              void* d_out, int out_size) {
    const float* x  = (const float*)d_in[0];
    const float* W1 = (const float*)d_in[1];
    const float* b1 = (const float*)d_in[2];
    const float* W2 = (const float*)d_in[3];
    const float* b2 = (const float*)d_in[4];
    const float* W3 = (const float*)d_in[5];
    const float* b3 = (const float*)d_in[6];
    const int*   ei = (const int*)d_in[7];   // int32 (JAX x64-disabled downcast)

    const int D0 = 1280;
    const int N = in_sizes[0] / D0;
    const int E = in_sizes[7] / 2;
    const int* src = ei;
    const int* dst = ei + E;

    __half *h16 = nullptr, *a16 = nullptr, *w1 = nullptr, *w2 = nullptr, *w3 = nullptr;
    cudaGetSymbolAddress((void**)&h16, g_h16);
    cudaGetSymbolAddress((void**)&a16, g_a16);
    cudaGetSymbolAddress((void**)&w1,  g_w1);
    cudaGetSymbolAddress((void**)&w2,  g_w2);
    cudaGetSymbolAddress((void**)&w3,  g_w3);

    static cudaStream_t s2 = nullptr;
    static cudaEvent_t evFork = nullptr, evW = nullptr, evCSR = nullptr;
    if (s2 == nullptr) {
        cudaStreamCreateWithFlags(&s2, cudaStreamNonBlocking);
        cudaEventCreateWithFlags(&evFork, cudaEventDisableTiming);
        cudaEventCreateWithFlags(&evW,    cudaEventDisableTiming);
        cudaEventCreateWithFlags(&evCSR,  cudaEventDisableTiming);
    }

    const int SMEM_BYTES = NSTAGE * STAGE_BYTES * 2;  // 110592
    cudaFuncSetAttribute(fp16_gemm, cudaFuncAttributeMaxDynamicSharedMemorySize,
                         SMEM_BYTES);

    const int T = 256;
    const int nbN = (N + T - 1) / T;
    const int nbE = (E + T - 1) / T;
    const int nbScan = (N + 255) / 256;
    const int ntm = MPAD / 128;  // 391
    const int totX = N * D0;

    // ---- fork side stream ----
    cudaEventRecord(evFork, 0);
    cudaStreamWaitEvent(s2, evFork, 0);

    // s2 phase 1: weight transposes
    k_wt<<<(512 * 1280 + 255) / 256, 256, 0, s2>>>(W1, w1, 1280, 512, 1280, 512);
    k_wt<<<(384 * 512 + 255) / 256, 256, 0, s2>>>(W2, w2, 512, 300, 512, 384);
    k_wt<<<(384 * 320 + 255) / 256, 256, 0, s2>>>(W3, w3, 300, 300, 320, 384);
    cudaEventRecord(evW, s2);

    // s2 phase 2: CSR build
    k_zero<<<nbN, T, 0, s2>>>(N);
    k_hist<<<nbE, T, 0, s2>>>(dst, E, N);
    k_scan_block<<<nbScan, 256, 0, s2>>>(N);
    k_scan_top<<<1, 256, 0, s2>>>(nbScan);
    k_finish<<<nbN, T, 0, s2>>>(N);
    k_fill<<<nbE, T, 0, s2>>>(src, dst, E, N);
    cudaEventRecord(evCSR, s2);

    // main stream: x conversion
    k_cvt<<<(totX / 4 + 255) / 256, 256>>>(x, a16, totX);

    // ---- Layer 1 ----
    cudaStreamWaitEvent(0, evW, 0);
    fp16_gemm<<<dim3(4, ntm), 256, SMEM_BYTES>>>(a16, 1280, w1, 1280, h16, N, 512, 1280);
    cudaStreamWaitEvent(0, evCSR, 0);
    k_agg4<512, 512, false><<<N, 128>>>(h16, b1, a16, nullptr);

    // ---- Layer 2 ----
    fp16_gemm<<<dim3(3, ntm), 256, SMEM_BYTES>>>(a16, 512, w2, 512, h16, N, 300, 512);
    k_agg4<300, 320, false><<<N, 96>>>(h16, b2, a16, nullptr);

    // ---- Layer 3 ----
    fp16_gemm<<<dim3(3, ntm), 256, SMEM_BYTES>>>(a16, 320, w3, 320, h16, N, 300, 320);
    k_agg4<300, 320, true><<<N, 96>>>(h16, b3, nullptr, (float*)d_out);
}